// round 13
// baseline (speedup 1.0000x reference)
#include <cuda.h>
#include <cuda_runtime.h>

// Warping_65094524339056 — Round 13: R12 (TMA tile staging, 48 warps,
// depth-3 ddf ring) + parity-paired ddf loads (LDG.64+LDG.32: 9->6
// wavefronts per warp-iter; all three ddf components come from 2
// instructions instead of 3 touching the same cache lines).

#define DMASK 127
#define H    4
#define EX   25
#define EY   17
#define EZV  41                  // valid z slots (used by ok-test)
#define SZ   44                  // TMA box z = 44 floats = 176 B
#define SXY  (EY*SZ)             // 748
#define TILE_ELEMS (EX*SXY)      // 18700 floats = 74800 B
#define NROWS (EX*EY)            // 425
#define TILE_BYTES (TILE_ELEMS*4)
#define BLOCK 512
#define VPT   8
#define PF    3

__device__ __forceinline__ float clampf(float v) {
    return fminf(fmaxf(v, 0.0f), 127.0f);
}

__device__ __forceinline__ unsigned smem_u32(const void* p) {
    unsigned a;
    asm("{ .reg .u64 t; cvta.to.shared.u64 t, %1; cvt.u32.u64 %0, t; }"
        : "=r"(a) : "l"(p));
    return a;
}

__global__ __launch_bounds__(BLOCK, 3) void warp_kernel(
    const float* __restrict__ ddf,
    const float* __restrict__ image,
    float* __restrict__ out,
    const __grid_constant__ CUtensorMap desc)
{
    extern __shared__ float tile[];
    unsigned sbase = smem_u32(tile);
    unsigned mbar  = sbase + TILE_BYTES;

    int tid = threadIdx.x;
    int bid = blockIdx.x;
    // 8(x) x 16(y) x 4(z) tiles x 4 batches = 2048 blocks
    int tz = bid & 3;
    int ty = (bid >> 2) & 15;
    int tx = (bid >> 6) & 7;
    int b  = bid >> 9;

    int X0 = tx << 4;
    int Y0 = ty << 3;
    int Z0 = tz << 5;

    const float* img = image + ((long long)b << 21);

    // ---- per-thread compute coords ----
    int lz  = tid & 31;
    int ly  = (tid >> 5) & 7;
    int lxh = tid >> 8;                // 0/1; x = X0 + lxh + 2*v
    int y = Y0 + ly;
    int z = Z0 + lz;
    int xb = X0 + lxh;

    int vid0 = (xb << 14) + (y << 7) + z;
    const float* ddfb = ddf + ((long long)b << 21) * 3;
    float*       outb = out + ((long long)b << 21);
    const float* dp0  = ddfb + (long long)vid0 * 3;

    // parity-paired ddf pointers: vid0 parity == lz parity; DSTRIDE even.
    // even lane: f2 @ dp0   -> (dx,dy),  s @ dp0+2 -> dz
    // odd  lane: f2 @ dp0+1 -> (dy,dz),  s @ dp0   -> dx
    int odd = lz & 1;
    const float2* dpa0 = (const float2*)(dp0 + odd);       // 8B-aligned
    const float*  dps0 = dp0 + (odd ? 0 : 2);
    const int DSTRIDE  = 3 << 15;      // ddf floats per x+=2 step (even)
    const int DSTRIDE2 = DSTRIDE / 2;  // float2 units

    if (tid == 0) {
        asm volatile("mbarrier.init.shared.b64 [%0], %1;"
                     :: "r"(mbar), "r"(1u) : "memory");
    }

    // ---- ddf prefetch ring: in flight while TMA runs ----
    float2 ra[PF];
    float  rs[PF];
#pragma unroll
    for (int p = 0; p < PF; p++) {
        ra[p] = __ldcs(dpa0 + p * DSTRIDE2);
        rs[p] = __ldcs(dps0 + p * DSTRIDE);
    }

    __syncthreads();   // mbarrier init visible

    if (tid == 0) {
        asm volatile("mbarrier.arrive.expect_tx.shared.b64 _, [%0], %1;"
                     :: "r"(mbar), "r"((unsigned)TILE_BYTES) : "memory");
        asm volatile(
            "cp.async.bulk.tensor.4d.shared::cta.global.tile.mbarrier::complete_tx::bytes "
            "[%0], [%1, {%2, %3, %4, %5}], [%6];"
            :: "r"(sbase), "l"(&desc),
               "r"(Z0 - H), "r"(Y0 - H), "r"(X0 - H), "r"(b),
               "r"(mbar)
            : "memory");
    }

    // ---- wait for the tile ----
    asm volatile(
        "{\n\t.reg .pred P;\n\t"
        "W_%=:\n\t"
        "mbarrier.try_wait.parity.shared.b64 P, [%0], %1;\n\t"
        "@!P bra W_%=;\n\t}"
        :: "r"(mbar), "r"(0u) : "memory");

    // ---- border fixups (block-uniform; x -> y -> z propagates corners) ----
    if (tx == 0) {
        for (int i = tid; i < 4 * SXY; i += BLOCK)
            tile[i] = tile[4 * SXY + (i % SXY)];
        __syncthreads();
    } else if (tx == 7) {
        for (int i = tid; i < 5 * SXY; i += BLOCK)
            tile[20 * SXY + i] = tile[19 * SXY + (i % SXY)];
        __syncthreads();
    }
    if (ty == 0) {
        for (int i = tid; i < EX * 4 * SZ; i += BLOCK) {
            int sx  = i / (4 * SZ);
            int rem = i - sx * (4 * SZ);
            tile[sx * SXY + rem] = tile[sx * SXY + 4 * SZ + (rem % SZ)];
        }
        __syncthreads();
    } else if (ty == 15) {
        for (int i = tid; i < EX * 5 * SZ; i += BLOCK) {
            int sx  = i / (5 * SZ);
            int rem = i - sx * (5 * SZ);
            tile[sx * SXY + 12 * SZ + rem] = tile[sx * SXY + 11 * SZ + (rem % SZ)];
        }
        __syncthreads();
    }
    if (tz == 0) {
        for (int r = tid; r < NROWS; r += BLOCK) {
            float v = tile[r * SZ + 4];
            tile[r * SZ + 0] = v;  tile[r * SZ + 1] = v;
            tile[r * SZ + 2] = v;  tile[r * SZ + 3] = v;
        }
        __syncthreads();
    } else if (tz == 3) {
        for (int r = tid; r < NROWS; r += BLOCK) {
            float v = tile[r * SZ + 35];
            tile[r * SZ + 36] = v;  tile[r * SZ + 37] = v;
            tile[r * SZ + 38] = v;  tile[r * SZ + 39] = v;
            tile[r * SZ + 40] = v;
        }
        __syncthreads();
    }

    const float yf = (float)y;
    const float zf = (float)z;
    const int ox = X0 - H, oy = Y0 - H, oz = Z0 - H;

#pragma unroll
    for (int v = 0; v < VPT; v++) {
        int slot = v % PF;
        float2 a = ra[slot];
        float  s = rs[slot];
        float dx = odd ? s   : a.x;
        float dy = odd ? a.x : a.y;
        float dz = odd ? a.y : s;

        if (v + PF < VPT) {
            ra[slot] = __ldcs(dpa0 + (v + PF) * DSTRIDE2);
            rs[slot] = __ldcs(dps0 + (v + PF) * DSTRIDE);
        }

        int vid = vid0 + (v << 15);

        float fx = (float)(xb + 2 * v) + dx;     // same fp as reference
        float fy = yf + dy;
        float fz = zf + dz;

        int ix0 = __float2int_rd(fx);
        int iy0 = __float2int_rd(fy);
        int iz0 = __float2int_rd(fz);
        float wx = fx - (float)ix0;
        float wy = fy - (float)iy0;
        float wz = fz - (float)iz0;

        int sx0 = ix0 - ox;
        int sy0 = iy0 - oy;
        int sz0 = iz0 - oz;

        bool ok = ((unsigned)sx0 <= (unsigned)(EX - 2)) &
                  ((unsigned)sy0 <= (unsigned)(EY - 2)) &
                  ((unsigned)sz0 <= (unsigned)(EZV - 2));

        float v000, v001, v010, v011, v100, v101, v110, v111;
        if (ok) {
            int base = (sx0 * EY + sy0) * SZ + sz0;
            v000 = tile[base];
            v001 = tile[base + 1];
            v010 = tile[base + SZ];
            v011 = tile[base + SZ + 1];
            v100 = tile[base + SXY];
            v101 = tile[base + SXY + 1];
            v110 = tile[base + SXY + SZ];
            v111 = tile[base + SXY + SZ + 1];
        } else {
            // rare: beyond halo -> clamped global gather (matches reference)
            float cfx = clampf(fx), cfy = clampf(fy), cfz = clampf(fz);
            ix0 = (int)cfx;  iy0 = (int)cfy;  iz0 = (int)cfz;
            wx = cfx - (float)ix0;
            wy = cfy - (float)iy0;
            wz = cfz - (float)iz0;
            int ix1 = min(ix0 + 1, DMASK);
            int iy1 = min(iy0 + 1, DMASK);
            int iz1 = min(iz0 + 1, DMASK);
            int g00 = (ix0 << 14) + (iy0 << 7);
            int g01 = (ix0 << 14) + (iy1 << 7);
            int g10 = (ix1 << 14) + (iy0 << 7);
            int g11 = (ix1 << 14) + (iy1 << 7);
            v000 = __ldg(img + g00 + iz0);  v001 = __ldg(img + g00 + iz1);
            v010 = __ldg(img + g01 + iz0);  v011 = __ldg(img + g01 + iz1);
            v100 = __ldg(img + g10 + iz0);  v101 = __ldg(img + g10 + iz1);
            v110 = __ldg(img + g11 + iz0);  v111 = __ldg(img + g11 + iz1);
        }

        float c00 = v000 + wz * (v001 - v000);
        float c01 = v010 + wz * (v011 - v010);
        float c10 = v100 + wz * (v101 - v100);
        float c11 = v110 + wz * (v111 - v110);
        float c0  = c00 + wy * (c01 - c00);
        float c1  = c10 + wy * (c11 - c10);
        __stcs(&outb[vid], c0 + wx * (c1 - c0));
    }
}

typedef CUresult (*EncodeTiledFn)(
    CUtensorMap*, CUtensorMapDataType, cuuint32_t, void*,
    const cuuint64_t*, const cuuint64_t*, const cuuint32_t*, const cuuint32_t*,
    CUtensorMapInterleave, CUtensorMapSwizzle, CUtensorMapL2promotion,
    CUtensorMapFloatOOBfill);

extern "C" void kernel_launch(void* const* d_in, const int* in_sizes, int n_in,
                              void* d_out, int out_size)
{
    const float* ddf   = (const float*)d_in[0];
    const float* image = (const float*)d_in[1];
    float* out = (float*)d_out;

    void* fp = nullptr;
    cudaDriverEntryPointQueryResult qres;
    cudaGetDriverEntryPoint("cuTensorMapEncodeTiled", &fp,
                            cudaEnableDefault, &qres);
    EncodeTiledFn encode = (EncodeTiledFn)fp;

    CUtensorMap desc;
    cuuint64_t dims[4]    = {128, 128, 128, 4};
    cuuint64_t strides[3] = {128ull * 4, 128ull * 128 * 4,
                             128ull * 128 * 128 * 4};
    cuuint32_t box[4]     = {SZ, EY, EX, 1};
    cuuint32_t estr[4]    = {1, 1, 1, 1};
    encode(&desc, CU_TENSOR_MAP_DATA_TYPE_FLOAT32, 4, (void*)image,
           dims, strides, box, estr,
           CU_TENSOR_MAP_INTERLEAVE_NONE, CU_TENSOR_MAP_SWIZZLE_NONE,
           CU_TENSOR_MAP_L2_PROMOTION_L2_128B,
           CU_TENSOR_MAP_FLOAT_OOB_FILL_NONE);

    size_t smem = TILE_BYTES + 16;
    cudaFuncSetAttribute(warp_kernel,
                         cudaFuncAttributeMaxDynamicSharedMemorySize, (int)smem);

    warp_kernel<<<2048, BLOCK, smem>>>(ddf, image, out, desc);
}